// round 6
// baseline (speedup 1.0000x reference)
#include <cuda_runtime.h>
#include <cstdint>

// ---------------------------------------------------------------------------
// patches [16384][9] f32, db [16384][9] f32.
// mask[i] = all_j ( dot(p_i,d_j) / (||p_i|| ||d_j||) < 0.9 )
// out = [ db (147456 f32) ; mask[i] ? p_i : 0 (147456 f32) ]
//
// 4 early-exit rounds over j (1/8, 1/8, 1/4, 1/2 of db) with worklist
// compaction between rounds; grid-stride x over the surviving patch list.
// ---------------------------------------------------------------------------

#define N_PATCH  16384
#define N_DB     16384
#define ROW      9
#define DUMMY    N_PATCH
#define HALF_OUT (N_DB * ROW)           // 147456
#define TOTAL_OUT (2 * HALF_OUT)        // 294912

typedef unsigned long long ull;

// db rows pre-normalized, duplicated for f32x2: [d0,d0,...,d8,d8,pad,pad]
__device__ ulonglong2 g_dn2[N_DB * 5];
// per-patch packed: 3 x float4 = [c0..c3][c4..c7][c8, thr, 0, 0]
__device__ float4 g_pp[(N_PATCH + 1) * 3];
__device__ int g_hit[N_PATCH];
__device__ int g_listA[N_PATCH];
__device__ int g_listB[N_PATCH];
__device__ int g_cnt[3];

// ------------------------- f32x2 helpers -----------------------------------
__device__ __forceinline__ ull pack2(float a, float b) {
    ull r; asm("mov.b64 %0, {%1, %2};" : "=l"(r) : "f"(a), "f"(b)); return r;
}
__device__ __forceinline__ ull fma2(ull a, ull b, ull c) {
    ull r; asm("fma.rn.f32x2 %0, %1, %2, %3;" : "=l"(r) : "l"(a), "l"(b), "l"(c));
    return r;
}
__device__ __forceinline__ ull mul2(ull a, ull b) {
    ull r; asm("mul.rn.f32x2 %0, %1, %2;" : "=l"(r) : "l"(a), "l"(b)); return r;
}

// ------------------------- prep kernel -------------------------------------
// fp32 norm accumulation; double only for the final sqrt/rsqrt (cheap).
__global__ void prep_kernel(const float* __restrict__ patches,
                            const float* __restrict__ db) {
    int idx = blockIdx.x * blockDim.x + threadIdx.x;
    if (idx < N_DB) {
        const float* s = db + idx * ROW;
        float v[ROW];
        float acc = 0.0f;
#pragma unroll
        for (int k = 0; k < ROW; k++) { v[k] = s[k]; acc = fmaf(v[k], v[k], acc); }
        float inv = (float)(1.0 / sqrt((double)acc));
        float* o = (float*)(g_dn2 + (size_t)idx * 5);
#pragma unroll
        for (int k = 0; k < ROW; k++) {
            float w = v[k] * inv;
            o[2 * k] = w; o[2 * k + 1] = w;
        }
        o[18] = 0.0f; o[19] = 0.0f;
        g_hit[idx] = 0;
        if (idx < 3) g_cnt[idx] = 0;
        if (idx == 0) {   // dummy patch: zero coords, huge threshold (never hits)
            float4 z = make_float4(0.f, 0.f, 0.f, 0.f);
            g_pp[DUMMY * 3 + 0] = z;
            g_pp[DUMMY * 3 + 1] = z;
            g_pp[DUMMY * 3 + 2] = make_float4(0.f, 1.0e30f, 0.f, 0.f);
        }
    } else if (idx < N_DB + N_PATCH) {
        int i = idx - N_DB;
        const float* s = patches + (size_t)i * ROW;
        float v[ROW];
        float acc = 0.0f;
#pragma unroll
        for (int k = 0; k < ROW; k++) { v[k] = s[k]; acc = fmaf(v[k], v[k], acc); }
        float thr = (float)(0.9 * sqrt((double)acc));
        g_pp[i * 3 + 0] = make_float4(v[0], v[1], v[2], v[3]);
        g_pp[i * 3 + 1] = make_float4(v[4], v[5], v[6], v[7]);
        g_pp[i * 3 + 2] = make_float4(v[8], thr, 0.f, 0.f);
    }
}

// ------------------------- similarity round --------------------------------
#define B_THREADS 256
#define NPAIR     2                      // pairs per thread = 4 patches
#define PPB       (B_THREADS * NPAIR * 2)   // 1024 patches per block-tile
#define JCHUNK    32
#define UNROLL    2

__global__ __launch_bounds__(B_THREADS)
void sim_kernel(int jbase, const int* __restrict__ list,
                const int* __restrict__ cntp) {
    const int tid = threadIdx.x;
    const int cnt = list ? *cntp : N_PATCH;
    const ulonglong2* __restrict__ dq0 =
        g_dn2 + (size_t)(jbase + blockIdx.y * JCHUNK) * 5;

    for (int base = blockIdx.x * PPB; base < cnt; base += gridDim.x * PPB) {
        // Resolve this thread's 4 patch indices (dummy beyond cnt)
        int ia[NPAIR], ib[NPAIR];
#pragma unroll
        for (int pr = 0; pr < NPAIR; pr++) {
            int s0 = base + tid * (2 * NPAIR) + 2 * pr;
            int s1 = s0 + 1;
            ia[pr] = (s0 < cnt) ? (list ? list[s0] : s0) : DUMMY;
            ib[pr] = (s1 < cnt) ? (list ? list[s1] : s1) : DUMMY;
        }

        // Pack pairs: 9 f32x2 coords + int thresholds
        ull pk[NPAIR][ROW];
        int tlo[NPAIR], thi[NPAIR];
#pragma unroll
        for (int pr = 0; pr < NPAIR; pr++) {
            float4 a0 = g_pp[ia[pr] * 3 + 0], a1 = g_pp[ia[pr] * 3 + 1],
                   a2 = g_pp[ia[pr] * 3 + 2];
            float4 b0 = g_pp[ib[pr] * 3 + 0], b1 = g_pp[ib[pr] * 3 + 1],
                   b2 = g_pp[ib[pr] * 3 + 2];
            pk[pr][0] = pack2(a0.x, b0.x); pk[pr][1] = pack2(a0.y, b0.y);
            pk[pr][2] = pack2(a0.z, b0.z); pk[pr][3] = pack2(a0.w, b0.w);
            pk[pr][4] = pack2(a1.x, b1.x); pk[pr][5] = pack2(a1.y, b1.y);
            pk[pr][6] = pack2(a1.z, b1.z); pk[pr][7] = pack2(a1.w, b1.w);
            pk[pr][8] = pack2(a2.x, b2.x);
            tlo[pr] = __float_as_int(a2.y);
            thi[pr] = __float_as_int(b2.y);
        }

        unsigned mlo[NPAIR], mhi[NPAIR];
#pragma unroll
        for (int pr = 0; pr < NPAIR; pr++) { mlo[pr] = 0xFFFFFFFFu; mhi[pr] = 0xFFFFFFFFu; }

        const ulonglong2* __restrict__ dq = dq0;
#pragma unroll 1
        for (int j = 0; j < JCHUNK; j += UNROLL) {
#pragma unroll
            for (int u = 0; u < UNROLL; u++) {
                const ulonglong2* q = dq + (size_t)u * 5;
                const ulonglong2 q0 = q[0];
                const ulonglong2 q1 = q[1];
                const ulonglong2 q2 = q[2];
                const ulonglong2 q3 = q[3];
                const ulonglong2 q4 = q[4];
#pragma unroll
                for (int pr = 0; pr < NPAIR; pr++) {
                    ull acc = mul2(pk[pr][0], q0.x);
                    acc = fma2(pk[pr][1], q0.y, acc);
                    acc = fma2(pk[pr][2], q1.x, acc);
                    acc = fma2(pk[pr][3], q1.y, acc);
                    acc = fma2(pk[pr][4], q2.x, acc);
                    acc = fma2(pk[pr][5], q2.y, acc);
                    acc = fma2(pk[pr][6], q3.x, acc);
                    acc = fma2(pk[pr][7], q3.y, acc);
                    acc = fma2(pk[pr][8], q4.x, acc);
                    // hit iff acc_half >= thr (thr > 0).
                    // acc >= 0: sign(lo - tlo) exact (no wrap possible).
                    // acc < 0: OR-ing lo's sign bit forces a miss, so any
                    // wrap in (lo - tlo) is harmless.
                    int lo = (int)(unsigned)acc;
                    int hi = (int)(acc >> 32);
                    mlo[pr] &= (unsigned)((lo - tlo[pr]) | lo);
                    mhi[pr] &= (unsigned)((hi - thi[pr]) | hi);
                }
            }
            dq += (size_t)UNROLL * 5;
        }

#pragma unroll
        for (int pr = 0; pr < NPAIR; pr++) {
            if (!(mlo[pr] & 0x80000000u) && ia[pr] < N_PATCH)
                ((volatile int*)g_hit)[ia[pr]] = 1;   // benign race: same value
            if (!(mhi[pr] & 0x80000000u) && ib[pr] < N_PATCH)
                ((volatile int*)g_hit)[ib[pr]] = 1;
        }
    }
}

// ------------------------- compaction --------------------------------------
__global__ void compact_kernel(int* __restrict__ outlist, int* __restrict__ cntslot) {
    int i = blockIdx.x * blockDim.x + threadIdx.x;
    bool surv = (i < N_PATCH) && (g_hit[i] == 0);
    unsigned ballot = __ballot_sync(0xFFFFFFFFu, surv);
    int lane = threadIdx.x & 31;
    int rank = __popc(ballot & ((1u << lane) - 1));
    int total = __popc(ballot);
    int basepos = 0;
    if (lane == 0 && total) basepos = atomicAdd(cntslot, total);
    basepos = __shfl_sync(0xFFFFFFFFu, basepos, 0);
    if (surv) outlist[basepos + rank] = i;
}

// ------------------------- output kernel -----------------------------------
__global__ void out_kernel(const float4* __restrict__ patches4,
                           const float4* __restrict__ db4,
                           float4* __restrict__ out4) {
    int idx = blockIdx.x * blockDim.x + threadIdx.x;
    if (idx < HALF_OUT / 4) {
        out4[idx] = db4[idx];
    } else if (idx < TOTAL_OUT / 4) {
        int t4 = idx - HALF_OUT / 4;
        float4 v = patches4[t4];
        float w[4] = {v.x, v.y, v.z, v.w};
        int t = t4 * 4;
#pragma unroll
        for (int k = 0; k < 4; k++)
            if (g_hit[(t + k) / ROW]) w[k] = 0.0f;
        out4[idx] = make_float4(w[0], w[1], w[2], w[3]);
    }
}

// ------------------------- launch ------------------------------------------
extern "C" void kernel_launch(void* const* d_in, const int* in_sizes, int n_in,
                              void* d_out, int out_size) {
    const float* patches = (const float*)d_in[0];   // [16384][9]
    const float* db      = (const float*)d_in[1];   // [16384][9]

    int *listA, *listB, *cnt;
    cudaGetSymbolAddress((void**)&listA, g_listA);
    cudaGetSymbolAddress((void**)&listB, g_listB);
    cudaGetSymbolAddress((void**)&cnt,   g_cnt);

    prep_kernel<<<(N_DB + N_PATCH + 255) / 256, 256>>>(patches, db);

    // Round 0: j [0, 2048), all patches
    sim_kernel<<<dim3(16, 64), B_THREADS>>>(0, nullptr, nullptr);
    compact_kernel<<<N_PATCH / 256, 256>>>(listA, cnt + 0);
    // Round 1: j [2048, 4096), survivors (E ~ 11k)
    sim_kernel<<<dim3(12, 64), B_THREADS>>>(2048, listA, cnt + 0);
    compact_kernel<<<N_PATCH / 256, 256>>>(listB, cnt + 1);
    // Round 2: j [4096, 8192), survivors (E ~ 7.7k)
    sim_kernel<<<dim3(8, 128), B_THREADS>>>(4096, listB, cnt + 1);
    compact_kernel<<<N_PATCH / 256, 256>>>(listA, cnt + 2);
    // Round 3: j [8192, 16384), survivors (E ~ 3.7k)
    sim_kernel<<<dim3(4, 256), B_THREADS>>>(8192, listA, cnt + 2);

    out_kernel<<<(TOTAL_OUT / 4 + 255) / 256, 256>>>(
        (const float4*)patches, (const float4*)db, (float4*)d_out);
}

// round 9
// speedup vs baseline: 1.5596x; 1.5596x over previous
#include <cuda_runtime.h>
#include <cstdint>

// ---------------------------------------------------------------------------
// patches [16384][9] f32, db [16384][9] f32.
// mask[i] = all_j ( dot(p_i,d_j) / (||p_i|| ||d_j||) < 0.9 )
// out = [ db (147456 f32) ; mask[i] ? p_i : 0 (147456 f32) ]
//
// 4 early-exit rounds over j (1/8, 1/8, 1/4, 1/2 of db) with worklist
// compaction between rounds; grid-stride x over the surviving patch list.
// ---------------------------------------------------------------------------

#define N_PATCH  16384
#define N_DB     16384
#define ROW      9
#define DUMMY    N_PATCH
#define HALF_OUT (N_DB * ROW)           // 147456
#define TOTAL_OUT (2 * HALF_OUT)        // 294912

typedef unsigned long long ull;

// db rows pre-normalized, duplicated for f32x2: [d0,d0,...,d8,d8,pad,pad]
__device__ ulonglong2 g_dn2[N_DB * 5];
// per-patch packed: 3 x float4 = [c0..c3][c4..c7][c8, thr, 0, 0]
__device__ float4 g_pp[(N_PATCH + 1) * 3];
__device__ int g_hit[N_PATCH];
__device__ int g_listA[N_PATCH];
__device__ int g_listB[N_PATCH];
__device__ int g_cnt[3];

// ------------------------- f32x2 helpers -----------------------------------
__device__ __forceinline__ ull pack2(float a, float b) {
    ull r; asm("mov.b64 %0, {%1, %2};" : "=l"(r) : "f"(a), "f"(b)); return r;
}
__device__ __forceinline__ ull fma2(ull a, ull b, ull c) {
    ull r; asm("fma.rn.f32x2 %0, %1, %2, %3;" : "=l"(r) : "l"(a), "l"(b), "l"(c));
    return r;
}
__device__ __forceinline__ ull mul2(ull a, ull b) {
    ull r; asm("mul.rn.f32x2 %0, %1, %2;" : "=l"(r) : "l"(a), "l"(b)); return r;
}
// max-accumulate both 32-bit halves of a packed f32x2 (two FMNMX, no extract)
__device__ __forceinline__ void max2(float& mlo, float& mhi, ull acc) {
    float lo, hi;
    asm("mov.b64 {%0, %1}, %2;" : "=f"(lo), "=f"(hi) : "l"(acc));
    mlo = fmaxf(mlo, lo);
    mhi = fmaxf(mhi, hi);
}

// ------------------------- prep kernel -------------------------------------
__global__ void prep_kernel(const float* __restrict__ patches,
                            const float* __restrict__ db) {
    int idx = blockIdx.x * blockDim.x + threadIdx.x;
    if (idx < N_DB) {
        const float* s = db + idx * ROW;
        float v[ROW];
        float acc = 0.0f;
#pragma unroll
        for (int k = 0; k < ROW; k++) { v[k] = s[k]; acc = fmaf(v[k], v[k], acc); }
        float inv = (float)(1.0 / sqrt((double)acc));
        float* o = (float*)(g_dn2 + (size_t)idx * 5);
#pragma unroll
        for (int k = 0; k < ROW; k++) {
            float w = v[k] * inv;
            o[2 * k] = w; o[2 * k + 1] = w;
        }
        o[18] = 0.0f; o[19] = 0.0f;
        g_hit[idx] = 0;
        if (idx < 3) g_cnt[idx] = 0;
        if (idx == 0) {   // dummy patch: zero coords, huge threshold (never hits)
            float4 z = make_float4(0.f, 0.f, 0.f, 0.f);
            g_pp[DUMMY * 3 + 0] = z;
            g_pp[DUMMY * 3 + 1] = z;
            g_pp[DUMMY * 3 + 2] = make_float4(0.f, 1.0e30f, 0.f, 0.f);
        }
    } else if (idx < N_DB + N_PATCH) {
        int i = idx - N_DB;
        const float* s = patches + (size_t)i * ROW;
        float v[ROW];
        float acc = 0.0f;
#pragma unroll
        for (int k = 0; k < ROW; k++) { v[k] = s[k]; acc = fmaf(v[k], v[k], acc); }
        float thr = (float)(0.9 * sqrt((double)acc));
        g_pp[i * 3 + 0] = make_float4(v[0], v[1], v[2], v[3]);
        g_pp[i * 3 + 1] = make_float4(v[4], v[5], v[6], v[7]);
        g_pp[i * 3 + 2] = make_float4(v[8], thr, 0.f, 0.f);
    }
}

// ------------------------- similarity round --------------------------------
#define B_THREADS 128
#define NPAIR     4                      // pairs per thread = 8 patches
#define PPB       (B_THREADS * NPAIR * 2)   // 1024 patches per block-tile
#define JCHUNK    32
#define UNROLL    2

__global__ __launch_bounds__(B_THREADS)
void sim_kernel(int jbase, const int* __restrict__ list,
                const int* __restrict__ cntp) {
    const int tid = threadIdx.x;
    const int cnt = list ? *cntp : N_PATCH;
    const ulonglong2* __restrict__ dq0 =
        g_dn2 + (size_t)(jbase + blockIdx.y * JCHUNK) * 5;

    for (int base = blockIdx.x * PPB; base < cnt; base += gridDim.x * PPB) {
        // Resolve this thread's 8 patch indices (dummy beyond cnt)
        int ia[NPAIR], ib[NPAIR];
#pragma unroll
        for (int pr = 0; pr < NPAIR; pr++) {
            int s0 = base + tid * (2 * NPAIR) + 2 * pr;
            int s1 = s0 + 1;
            ia[pr] = (s0 < cnt) ? (list ? list[s0] : s0) : DUMMY;
            ib[pr] = (s1 < cnt) ? (list ? list[s1] : s1) : DUMMY;
        }

        // Pack pairs: 9 f32x2 coords + float thresholds
        ull pk[NPAIR][ROW];
        float tA[NPAIR], tB[NPAIR];
#pragma unroll
        for (int pr = 0; pr < NPAIR; pr++) {
            float4 a0 = g_pp[ia[pr] * 3 + 0], a1 = g_pp[ia[pr] * 3 + 1],
                   a2 = g_pp[ia[pr] * 3 + 2];
            float4 b0 = g_pp[ib[pr] * 3 + 0], b1 = g_pp[ib[pr] * 3 + 1],
                   b2 = g_pp[ib[pr] * 3 + 2];
            pk[pr][0] = pack2(a0.x, b0.x); pk[pr][1] = pack2(a0.y, b0.y);
            pk[pr][2] = pack2(a0.z, b0.z); pk[pr][3] = pack2(a0.w, b0.w);
            pk[pr][4] = pack2(a1.x, b1.x); pk[pr][5] = pack2(a1.y, b1.y);
            pk[pr][6] = pack2(a1.z, b1.z); pk[pr][7] = pack2(a1.w, b1.w);
            pk[pr][8] = pack2(a2.x, b2.x);
            tA[pr] = a2.y;
            tB[pr] = b2.y;
        }

        float mA[NPAIR], mB[NPAIR];
#pragma unroll
        for (int pr = 0; pr < NPAIR; pr++) { mA[pr] = -3.0e38f; mB[pr] = -3.0e38f; }

        const ulonglong2* __restrict__ dq = dq0;
#pragma unroll 1
        for (int j = 0; j < JCHUNK; j += UNROLL) {
#pragma unroll
            for (int u = 0; u < UNROLL; u++) {
                const ulonglong2* q = dq + (size_t)u * 5;
                const ulonglong2 q0 = q[0];
                const ulonglong2 q1 = q[1];
                const ulonglong2 q2 = q[2];
                const ulonglong2 q3 = q[3];
                const ulonglong2 q4 = q[4];
#pragma unroll
                for (int pr = 0; pr < NPAIR; pr++) {
                    ull acc = mul2(pk[pr][0], q0.x);
                    acc = fma2(pk[pr][1], q0.y, acc);
                    acc = fma2(pk[pr][2], q1.x, acc);
                    acc = fma2(pk[pr][3], q1.y, acc);
                    acc = fma2(pk[pr][4], q2.x, acc);
                    acc = fma2(pk[pr][5], q2.y, acc);
                    acc = fma2(pk[pr][6], q3.x, acc);
                    acc = fma2(pk[pr][7], q3.y, acc);
                    acc = fma2(pk[pr][8], q4.x, acc);
                    max2(mA[pr], mB[pr], acc);   // 2 FMNMX on the reg pair
                }
            }
            dq += (size_t)UNROLL * 5;
        }

#pragma unroll
        for (int pr = 0; pr < NPAIR; pr++) {
            if (mA[pr] >= tA[pr] && ia[pr] < N_PATCH)
                ((volatile int*)g_hit)[ia[pr]] = 1;   // benign race: same value
            if (mB[pr] >= tB[pr] && ib[pr] < N_PATCH)
                ((volatile int*)g_hit)[ib[pr]] = 1;
        }
    }
}

// ------------------------- compaction --------------------------------------
__global__ void compact_kernel(int* __restrict__ outlist, int* __restrict__ cntslot) {
    int i = blockIdx.x * blockDim.x + threadIdx.x;
    bool surv = (i < N_PATCH) && (g_hit[i] == 0);
    unsigned ballot = __ballot_sync(0xFFFFFFFFu, surv);
    int lane = threadIdx.x & 31;
    int rank = __popc(ballot & ((1u << lane) - 1));
    int total = __popc(ballot);
    int basepos = 0;
    if (lane == 0 && total) basepos = atomicAdd(cntslot, total);
    basepos = __shfl_sync(0xFFFFFFFFu, basepos, 0);
    if (surv) outlist[basepos + rank] = i;
}

// ------------------------- output kernel -----------------------------------
__global__ void out_kernel(const float4* __restrict__ patches4,
                           const float4* __restrict__ db4,
                           float4* __restrict__ out4) {
    int idx = blockIdx.x * blockDim.x + threadIdx.x;
    if (idx < HALF_OUT / 4) {
        out4[idx] = db4[idx];
    } else if (idx < TOTAL_OUT / 4) {
        int t4 = idx - HALF_OUT / 4;
        float4 v = patches4[t4];
        float w[4] = {v.x, v.y, v.z, v.w};
        int t = t4 * 4;
#pragma unroll
        for (int k = 0; k < 4; k++)
            if (g_hit[(t + k) / ROW]) w[k] = 0.0f;
        out4[idx] = make_float4(w[0], w[1], w[2], w[3]);
    }
}

// ------------------------- launch ------------------------------------------
extern "C" void kernel_launch(void* const* d_in, const int* in_sizes, int n_in,
                              void* d_out, int out_size) {
    const float* patches = (const float*)d_in[0];   // [16384][9]
    const float* db      = (const float*)d_in[1];   // [16384][9]

    int *listA, *listB, *cnt;
    cudaGetSymbolAddress((void**)&listA, g_listA);
    cudaGetSymbolAddress((void**)&listB, g_listB);
    cudaGetSymbolAddress((void**)&cnt,   g_cnt);

    prep_kernel<<<(N_DB + N_PATCH + 255) / 256, 256>>>(patches, db);

    // Round 0: j [0, 2048), all patches        -> 16 x 64 = 1024 blocks
    sim_kernel<<<dim3(16, 64), B_THREADS>>>(0, nullptr, nullptr);
    compact_kernel<<<N_PATCH / 256, 256>>>(listA, cnt + 0);
    // Round 1: j [2048, 4096), survivors       -> 16 x 64
    sim_kernel<<<dim3(16, 64), B_THREADS>>>(2048, listA, cnt + 0);
    compact_kernel<<<N_PATCH / 256, 256>>>(listB, cnt + 1);
    // Round 2: j [4096, 8192), survivors       -> 8 x 128
    sim_kernel<<<dim3(8, 128), B_THREADS>>>(4096, listB, cnt + 1);
    compact_kernel<<<N_PATCH / 256, 256>>>(listA, cnt + 2);
    // Round 3: j [8192, 16384), survivors      -> 4 x 256
    sim_kernel<<<dim3(4, 256), B_THREADS>>>(8192, listA, cnt + 2);

    out_kernel<<<(TOTAL_OUT / 4 + 255) / 256, 256>>>(
        (const float4*)patches, (const float4*)db, (float4*)d_out);
}

// round 11
// speedup vs baseline: 1.7866x; 1.1455x over previous
#include <cuda_runtime.h>
#include <cstdint>

// ---------------------------------------------------------------------------
// patches [16384][9] f32, db [16384][9] f32.
// mask[i] = all_j ( dot(p_i,d_j) / (||p_i|| ||d_j||) < 0.9 )
// out = [ db (147456 f32) ; mask[i] ? p_i : 0 (147456 f32) ]
//
// 4 early-exit rounds over j (1/8, 1/8, 1/4, 1/2 of db) with worklist
// compaction; db tile staged in shared memory (LDS broadcast in inner loop).
// ---------------------------------------------------------------------------

#define N_PATCH  16384
#define N_DB     16384
#define ROW      9
#define DUMMY    N_PATCH
#define HALF_OUT (N_DB * ROW)           // 147456
#define TOTAL_OUT (2 * HALF_OUT)        // 294912

typedef unsigned long long ull;

// db rows pre-normalized, duplicated for f32x2: [d0,d0,...,d8,d8,pad,pad]
__device__ ulonglong2 g_dn2[N_DB * 5];
// per-patch packed: 3 x float4 = [c0..c3][c4..c7][c8, thr, 0, 0]
__device__ float4 g_pp[(N_PATCH + 1) * 3];
__device__ int g_hit[N_PATCH];
__device__ int g_listA[N_PATCH];
__device__ int g_listB[N_PATCH];
__device__ int g_cnt[3];

// ------------------------- f32x2 helpers -----------------------------------
__device__ __forceinline__ ull pack2(float a, float b) {
    ull r; asm("mov.b64 %0, {%1, %2};" : "=l"(r) : "f"(a), "f"(b)); return r;
}
__device__ __forceinline__ ull fma2(ull a, ull b, ull c) {
    ull r; asm("fma.rn.f32x2 %0, %1, %2, %3;" : "=l"(r) : "l"(a), "l"(b), "l"(c));
    return r;
}
__device__ __forceinline__ ull mul2(ull a, ull b) {
    ull r; asm("mul.rn.f32x2 %0, %1, %2;" : "=l"(r) : "l"(a), "l"(b)); return r;
}
// max-accumulate both 32-bit halves of a packed f32x2 (two FMNMX, no extract)
__device__ __forceinline__ void max2(float& mlo, float& mhi, ull acc) {
    float lo, hi;
    asm("mov.b64 {%0, %1}, %2;" : "=f"(lo), "=f"(hi) : "l"(acc));
    mlo = fmaxf(mlo, lo);
    mhi = fmaxf(mhi, hi);
}

// ------------------------- prep kernel -------------------------------------
__global__ void prep_kernel(const float* __restrict__ patches,
                            const float* __restrict__ db) {
    int idx = blockIdx.x * blockDim.x + threadIdx.x;
    if (idx < N_DB) {
        const float* s = db + idx * ROW;
        float v[ROW];
        float acc = 0.0f;
#pragma unroll
        for (int k = 0; k < ROW; k++) { v[k] = s[k]; acc = fmaf(v[k], v[k], acc); }
        float inv = (float)(1.0 / sqrt((double)acc));
        float* o = (float*)(g_dn2 + (size_t)idx * 5);
#pragma unroll
        for (int k = 0; k < ROW; k++) {
            float w = v[k] * inv;
            o[2 * k] = w; o[2 * k + 1] = w;
        }
        o[18] = 0.0f; o[19] = 0.0f;
        g_hit[idx] = 0;
        if (idx < 3) g_cnt[idx] = 0;
        if (idx == 0) {   // dummy patch: zero coords, huge threshold (never hits)
            float4 z = make_float4(0.f, 0.f, 0.f, 0.f);
            g_pp[DUMMY * 3 + 0] = z;
            g_pp[DUMMY * 3 + 1] = z;
            g_pp[DUMMY * 3 + 2] = make_float4(0.f, 1.0e30f, 0.f, 0.f);
        }
    } else if (idx < N_DB + N_PATCH) {
        int i = idx - N_DB;
        const float* s = patches + (size_t)i * ROW;
        float v[ROW];
        float acc = 0.0f;
#pragma unroll
        for (int k = 0; k < ROW; k++) { v[k] = s[k]; acc = fmaf(v[k], v[k], acc); }
        float thr = (float)(0.9 * sqrt((double)acc));
        g_pp[i * 3 + 0] = make_float4(v[0], v[1], v[2], v[3]);
        g_pp[i * 3 + 1] = make_float4(v[4], v[5], v[6], v[7]);
        g_pp[i * 3 + 2] = make_float4(v[8], thr, 0.f, 0.f);
    }
}

// ------------------------- similarity round --------------------------------
#define B_THREADS 128
#define NPAIR     4                      // pairs per thread = 8 patches
#define PPB       (B_THREADS * NPAIR * 2)   // 1024 patches per x-tile
#define JCHUNK    64
#define UNROLL    2

__global__ __launch_bounds__(B_THREADS)
void sim_kernel(int jbase, const int* __restrict__ list,
                const int* __restrict__ cntp) {
    __shared__ ulonglong2 s_db[JCHUNK * 5];          // 5 KB db tile

    const int tid = threadIdx.x;
    const int cnt = list ? *cntp : N_PATCH;

    // Cooperative tile load: 320 x 16B, depends only on blockIdx.y
    {
        const ulonglong2* src = g_dn2 + (size_t)(jbase + blockIdx.y * JCHUNK) * 5;
#pragma unroll
        for (int t = 0; t < 3; t++) {
            int k = tid + t * B_THREADS;
            if (k < JCHUNK * 5) s_db[k] = src[k];
        }
    }
    __syncthreads();

    for (int base = blockIdx.x * PPB; base < cnt; base += gridDim.x * PPB) {
        // Resolve this thread's 8 patch indices (dummy beyond cnt)
        int ia[NPAIR], ib[NPAIR];
#pragma unroll
        for (int pr = 0; pr < NPAIR; pr++) {
            int s0 = base + tid * (2 * NPAIR) + 2 * pr;
            int s1 = s0 + 1;
            ia[pr] = (s0 < cnt) ? (list ? list[s0] : s0) : DUMMY;
            ib[pr] = (s1 < cnt) ? (list ? list[s1] : s1) : DUMMY;
        }

        // Pack pairs: 9 f32x2 coords + float thresholds
        ull pk[NPAIR][ROW];
        float tA[NPAIR], tB[NPAIR];
#pragma unroll
        for (int pr = 0; pr < NPAIR; pr++) {
            float4 a0 = g_pp[ia[pr] * 3 + 0], a1 = g_pp[ia[pr] * 3 + 1],
                   a2 = g_pp[ia[pr] * 3 + 2];
            float4 b0 = g_pp[ib[pr] * 3 + 0], b1 = g_pp[ib[pr] * 3 + 1],
                   b2 = g_pp[ib[pr] * 3 + 2];
            pk[pr][0] = pack2(a0.x, b0.x); pk[pr][1] = pack2(a0.y, b0.y);
            pk[pr][2] = pack2(a0.z, b0.z); pk[pr][3] = pack2(a0.w, b0.w);
            pk[pr][4] = pack2(a1.x, b1.x); pk[pr][5] = pack2(a1.y, b1.y);
            pk[pr][6] = pack2(a1.z, b1.z); pk[pr][7] = pack2(a1.w, b1.w);
            pk[pr][8] = pack2(a2.x, b2.x);
            tA[pr] = a2.y;
            tB[pr] = b2.y;
        }

        float mA[NPAIR], mB[NPAIR];
#pragma unroll
        for (int pr = 0; pr < NPAIR; pr++) { mA[pr] = -3.0e38f; mB[pr] = -3.0e38f; }

#pragma unroll 1
        for (int j = 0; j < JCHUNK; j += UNROLL) {
#pragma unroll
            for (int u = 0; u < UNROLL; u++) {
                const ulonglong2* q = s_db + (j + u) * 5;
                const ulonglong2 q0 = q[0];
                const ulonglong2 q1 = q[1];
                const ulonglong2 q2 = q[2];
                const ulonglong2 q3 = q[3];
                const ulonglong2 q4 = q[4];
#pragma unroll
                for (int pr = 0; pr < NPAIR; pr++) {
                    ull acc = mul2(pk[pr][0], q0.x);
                    acc = fma2(pk[pr][1], q0.y, acc);
                    acc = fma2(pk[pr][2], q1.x, acc);
                    acc = fma2(pk[pr][3], q1.y, acc);
                    acc = fma2(pk[pr][4], q2.x, acc);
                    acc = fma2(pk[pr][5], q2.y, acc);
                    acc = fma2(pk[pr][6], q3.x, acc);
                    acc = fma2(pk[pr][7], q3.y, acc);
                    acc = fma2(pk[pr][8], q4.x, acc);
                    max2(mA[pr], mB[pr], acc);   // 2 FMNMX on the reg pair
                }
            }
        }

#pragma unroll
        for (int pr = 0; pr < NPAIR; pr++) {
            if (mA[pr] >= tA[pr] && ia[pr] < N_PATCH)
                ((volatile int*)g_hit)[ia[pr]] = 1;   // benign race: same value
            if (mB[pr] >= tB[pr] && ib[pr] < N_PATCH)
                ((volatile int*)g_hit)[ib[pr]] = 1;
        }
    }
}

// ------------------------- compaction --------------------------------------
__global__ void compact_kernel(int* __restrict__ outlist, int* __restrict__ cntslot) {
    int i = blockIdx.x * blockDim.x + threadIdx.x;
    bool surv = (i < N_PATCH) && (g_hit[i] == 0);
    unsigned ballot = __ballot_sync(0xFFFFFFFFu, surv);
    int lane = threadIdx.x & 31;
    int rank = __popc(ballot & ((1u << lane) - 1));
    int total = __popc(ballot);
    int basepos = 0;
    if (lane == 0 && total) basepos = atomicAdd(cntslot, total);
    basepos = __shfl_sync(0xFFFFFFFFu, basepos, 0);
    if (surv) outlist[basepos + rank] = i;
}

// ------------------------- output kernel -----------------------------------
__global__ void out_kernel(const float4* __restrict__ patches4,
                           const float4* __restrict__ db4,
                           float4* __restrict__ out4) {
    int idx = blockIdx.x * blockDim.x + threadIdx.x;
    if (idx < HALF_OUT / 4) {
        out4[idx] = db4[idx];
    } else if (idx < TOTAL_OUT / 4) {
        int t4 = idx - HALF_OUT / 4;
        float4 v = patches4[t4];
        float w[4] = {v.x, v.y, v.z, v.w};
        int t = t4 * 4;
#pragma unroll
        for (int k = 0; k < 4; k++)
            if (g_hit[(t + k) / ROW]) w[k] = 0.0f;
        out4[idx] = make_float4(w[0], w[1], w[2], w[3]);
    }
}

// ------------------------- launch ------------------------------------------
extern "C" void kernel_launch(void* const* d_in, const int* in_sizes, int n_in,
                              void* d_out, int out_size) {
    const float* patches = (const float*)d_in[0];   // [16384][9]
    const float* db      = (const float*)d_in[1];   // [16384][9]

    int *listA, *listB, *cnt;
    cudaGetSymbolAddress((void**)&listA, g_listA);
    cudaGetSymbolAddress((void**)&listB, g_listB);
    cudaGetSymbolAddress((void**)&cnt,   g_cnt);

    prep_kernel<<<(N_DB + N_PATCH + 255) / 256, 256>>>(patches, db);

    // Round 0: j [0, 2048), all patches        -> 16 x 32 = 512 blocks
    sim_kernel<<<dim3(16, 32), B_THREADS>>>(0, nullptr, nullptr);
    compact_kernel<<<N_PATCH / 256, 256>>>(listA, cnt + 0);
    // Round 1: j [2048, 4096), survivors       -> 16 x 32
    sim_kernel<<<dim3(16, 32), B_THREADS>>>(2048, listA, cnt + 0);
    compact_kernel<<<N_PATCH / 256, 256>>>(listB, cnt + 1);
    // Round 2: j [4096, 8192), survivors       -> 8 x 64
    sim_kernel<<<dim3(8, 64), B_THREADS>>>(4096, listB, cnt + 1);
    compact_kernel<<<N_PATCH / 256, 256>>>(listA, cnt + 2);
    // Round 3: j [8192, 16384), survivors      -> 4 x 128
    sim_kernel<<<dim3(4, 128), B_THREADS>>>(8192, listA, cnt + 2);

    out_kernel<<<(TOTAL_OUT / 4 + 255) / 256, 256>>>(
        (const float4*)patches, (const float4*)db, (float4*)d_out);
}

// round 13
// speedup vs baseline: 2.0396x; 1.1416x over previous
#include <cuda_runtime.h>
#include <cstdint>

// ---------------------------------------------------------------------------
// patches [16384][9] f32, db [16384][9] f32.
// mask[i] = all_j ( dot(p_i,d_j) / (||p_i|| ||d_j||) < 0.9 )
// out = [ db (147456 f32) ; mask[i] ? p_i : 0 (147456 f32) ]
//
// 4 early-exit rounds over j with worklist compaction; db tile in smem;
// threshold folded into the FMA chain, miss tracked via sign-bit AND.
// ---------------------------------------------------------------------------

#define N_PATCH  16384
#define N_DB     16384
#define ROW      9
#define DUMMY    N_PATCH
#define HALF_OUT (N_DB * ROW)           // 147456
#define TOTAL_OUT (2 * HALF_OUT)        // 294912

typedef unsigned long long ull;

// db rows pre-normalized, duplicated for f32x2: [d0,d0,...,d8,d8,pad,pad]
__device__ ulonglong2 g_dn2[N_DB * 5];
// per-patch packed: 3 x float4 = [c0..c3][c4..c7][c8, -thr, 0, 0]
__device__ float4 g_pp[(N_PATCH + 1) * 3];
__device__ int g_hit[N_PATCH];
__device__ int g_listA[N_PATCH];
__device__ int g_listB[N_PATCH];
__device__ int g_cnt[3];

// ------------------------- f32x2 helpers -----------------------------------
__device__ __forceinline__ ull pack2(float a, float b) {
    ull r; asm("mov.b64 %0, {%1, %2};" : "=l"(r) : "f"(a), "f"(b)); return r;
}
__device__ __forceinline__ ull fma2(ull a, ull b, ull c) {
    ull r; asm("fma.rn.f32x2 %0, %1, %2, %3;" : "=l"(r) : "l"(a), "l"(b), "l"(c));
    return r;
}

// ------------------------- prep kernel -------------------------------------
__global__ void prep_kernel(const float* __restrict__ patches,
                            const float* __restrict__ db) {
    int idx = blockIdx.x * blockDim.x + threadIdx.x;
    if (idx < N_DB) {
        const float* s = db + idx * ROW;
        float v[ROW];
        float acc = 0.0f;
#pragma unroll
        for (int k = 0; k < ROW; k++) { v[k] = s[k]; acc = fmaf(v[k], v[k], acc); }
        float inv = (float)(1.0 / sqrt((double)acc));
        float* o = (float*)(g_dn2 + (size_t)idx * 5);
#pragma unroll
        for (int k = 0; k < ROW; k++) {
            float w = v[k] * inv;
            o[2 * k] = w; o[2 * k + 1] = w;
        }
        o[18] = 0.0f; o[19] = 0.0f;
        g_hit[idx] = 0;
        if (idx < 3) g_cnt[idx] = 0;
        if (idx == 0) {   // dummy patch: zero coords, -thr = -1e30 (never hits)
            float4 z = make_float4(0.f, 0.f, 0.f, 0.f);
            g_pp[DUMMY * 3 + 0] = z;
            g_pp[DUMMY * 3 + 1] = z;
            g_pp[DUMMY * 3 + 2] = make_float4(0.f, -1.0e30f, 0.f, 0.f);
        }
    } else if (idx < N_DB + N_PATCH) {
        int i = idx - N_DB;
        const float* s = patches + (size_t)i * ROW;
        float v[ROW];
        float acc = 0.0f;
#pragma unroll
        for (int k = 0; k < ROW; k++) { v[k] = s[k]; acc = fmaf(v[k], v[k], acc); }
        float negthr = -(float)(0.9 * sqrt((double)acc));
        g_pp[i * 3 + 0] = make_float4(v[0], v[1], v[2], v[3]);
        g_pp[i * 3 + 1] = make_float4(v[4], v[5], v[6], v[7]);
        g_pp[i * 3 + 2] = make_float4(v[8], negthr, 0.f, 0.f);
    }
}

// ------------------------- similarity round --------------------------------
#define B_THREADS 128
#define NPAIR     4                      // pairs per thread = 8 patches
#define PPB       (B_THREADS * NPAIR * 2)   // 1024 patches per x-tile
#define JCHUNK    32
#define UNROLL    2

__global__ __launch_bounds__(B_THREADS)
void sim_kernel(int jbase, const int* __restrict__ list,
                const int* __restrict__ cntp) {
    __shared__ ulonglong2 s_db[JCHUNK * 5];          // 2.5 KB db tile

    const int tid = threadIdx.x;
    const int cnt = list ? *cntp : N_PATCH;

    // Cooperative tile load: 160 x 16B, depends only on blockIdx.y
    {
        const ulonglong2* src = g_dn2 + (size_t)(jbase + blockIdx.y * JCHUNK) * 5;
#pragma unroll
        for (int t = 0; t < 2; t++) {
            int k = tid + t * B_THREADS;
            if (k < JCHUNK * 5) s_db[k] = src[k];
        }
    }
    __syncthreads();

    for (int base = blockIdx.x * PPB; base < cnt; base += gridDim.x * PPB) {
        // Resolve this thread's 8 patch indices (dummy beyond cnt)
        int ia[NPAIR], ib[NPAIR];
#pragma unroll
        for (int pr = 0; pr < NPAIR; pr++) {
            int s0 = base + tid * (2 * NPAIR) + 2 * pr;
            int s1 = s0 + 1;
            ia[pr] = (s0 < cnt) ? (list ? list[s0] : s0) : DUMMY;
            ib[pr] = (s1 < cnt) ? (list ? list[s1] : s1) : DUMMY;
        }

        // Pack pairs: 9 f32x2 coords + packed negated thresholds
        ull pk[NPAIR][ROW];
        ull negt[NPAIR];
#pragma unroll
        for (int pr = 0; pr < NPAIR; pr++) {
            float4 a0 = g_pp[ia[pr] * 3 + 0], a1 = g_pp[ia[pr] * 3 + 1],
                   a2 = g_pp[ia[pr] * 3 + 2];
            float4 b0 = g_pp[ib[pr] * 3 + 0], b1 = g_pp[ib[pr] * 3 + 1],
                   b2 = g_pp[ib[pr] * 3 + 2];
            pk[pr][0] = pack2(a0.x, b0.x); pk[pr][1] = pack2(a0.y, b0.y);
            pk[pr][2] = pack2(a0.z, b0.z); pk[pr][3] = pack2(a0.w, b0.w);
            pk[pr][4] = pack2(a1.x, b1.x); pk[pr][5] = pack2(a1.y, b1.y);
            pk[pr][6] = pack2(a1.z, b1.z); pk[pr][7] = pack2(a1.w, b1.w);
            pk[pr][8] = pack2(a2.x, b2.x);
            negt[pr]  = pack2(a2.y, b2.y);   // (-thrA, -thrB)
        }

        // all-miss sign accumulators: sign bit stays 1 iff every j missed
        unsigned mlo[NPAIR], mhi[NPAIR];
#pragma unroll
        for (int pr = 0; pr < NPAIR; pr++) { mlo[pr] = 0xFFFFFFFFu; mhi[pr] = 0xFFFFFFFFu; }

#pragma unroll 1
        for (int j = 0; j < JCHUNK; j += UNROLL) {
#pragma unroll
            for (int u = 0; u < UNROLL; u++) {
                const ulonglong2* q = s_db + (j + u) * 5;
                const ulonglong2 q0 = q[0];
                const ulonglong2 q1 = q[1];
                const ulonglong2 q2 = q[2];
                const ulonglong2 q3 = q[3];
                const ulonglong2 q4 = q[4];
#pragma unroll
                for (int pr = 0; pr < NPAIR; pr++) {
                    // acc = dot - thr (both halves); hit iff acc >= +0
                    ull acc = fma2(pk[pr][0], q0.x, negt[pr]);
                    acc = fma2(pk[pr][1], q0.y, acc);
                    acc = fma2(pk[pr][2], q1.x, acc);
                    acc = fma2(pk[pr][3], q1.y, acc);
                    acc = fma2(pk[pr][4], q2.x, acc);
                    acc = fma2(pk[pr][5], q2.y, acc);
                    acc = fma2(pk[pr][6], q3.x, acc);
                    acc = fma2(pk[pr][7], q3.y, acc);
                    acc = fma2(pk[pr][8], q4.x, acc);
                    mlo[pr] &= (unsigned)acc;          // LOP3 on low reg
                    mhi[pr] &= (unsigned)(acc >> 32);  // LOP3 on high reg
                }
            }
        }

#pragma unroll
        for (int pr = 0; pr < NPAIR; pr++) {
            if (!(mlo[pr] & 0x80000000u) && ia[pr] < N_PATCH)
                ((volatile int*)g_hit)[ia[pr]] = 1;   // benign race: same value
            if (!(mhi[pr] & 0x80000000u) && ib[pr] < N_PATCH)
                ((volatile int*)g_hit)[ib[pr]] = 1;
        }
    }
}

// ------------------------- compaction --------------------------------------
__global__ void compact_kernel(int* __restrict__ outlist, int* __restrict__ cntslot) {
    int i = blockIdx.x * blockDim.x + threadIdx.x;
    bool surv = (i < N_PATCH) && (g_hit[i] == 0);
    unsigned ballot = __ballot_sync(0xFFFFFFFFu, surv);
    int lane = threadIdx.x & 31;
    int rank = __popc(ballot & ((1u << lane) - 1));
    int total = __popc(ballot);
    int basepos = 0;
    if (lane == 0 && total) basepos = atomicAdd(cntslot, total);
    basepos = __shfl_sync(0xFFFFFFFFu, basepos, 0);
    if (surv) outlist[basepos + rank] = i;
}

// ------------------------- output kernel -----------------------------------
__global__ void out_kernel(const float4* __restrict__ patches4,
                           const float4* __restrict__ db4,
                           float4* __restrict__ out4) {
    int idx = blockIdx.x * blockDim.x + threadIdx.x;
    if (idx < HALF_OUT / 4) {
        out4[idx] = db4[idx];
    } else if (idx < TOTAL_OUT / 4) {
        int t4 = idx - HALF_OUT / 4;
        float4 v = patches4[t4];
        float w[4] = {v.x, v.y, v.z, v.w};
        int t = t4 * 4;
#pragma unroll
        for (int k = 0; k < 4; k++)
            if (g_hit[(t + k) / ROW]) w[k] = 0.0f;
        out4[idx] = make_float4(w[0], w[1], w[2], w[3]);
    }
}

// ------------------------- launch ------------------------------------------
extern "C" void kernel_launch(void* const* d_in, const int* in_sizes, int n_in,
                              void* d_out, int out_size) {
    const float* patches = (const float*)d_in[0];   // [16384][9]
    const float* db      = (const float*)d_in[1];   // [16384][9]

    int *listA, *listB, *cnt;
    cudaGetSymbolAddress((void**)&listA, g_listA);
    cudaGetSymbolAddress((void**)&listB, g_listB);
    cudaGetSymbolAddress((void**)&cnt,   g_cnt);

    prep_kernel<<<(N_DB + N_PATCH + 255) / 256, 256>>>(patches, db);

    // Round 0: j [0, 2048), all patches        -> 16 x 64 = 1024 blocks
    sim_kernel<<<dim3(16, 64), B_THREADS>>>(0, nullptr, nullptr);
    compact_kernel<<<N_PATCH / 256, 256>>>(listA, cnt + 0);
    // Round 1: j [2048, 4096), survivors       -> 16 x 64
    sim_kernel<<<dim3(16, 64), B_THREADS>>>(2048, listA, cnt + 0);
    compact_kernel<<<N_PATCH / 256, 256>>>(listB, cnt + 1);
    // Round 2: j [4096, 8192), survivors       -> 8 x 128
    sim_kernel<<<dim3(8, 128), B_THREADS>>>(4096, listB, cnt + 1);
    compact_kernel<<<N_PATCH / 256, 256>>>(listA, cnt + 2);
    // Round 3: j [8192, 16384), survivors      -> 4 x 256
    sim_kernel<<<dim3(4, 256), B_THREADS>>>(8192, listA, cnt + 2);

    out_kernel<<<(TOTAL_OUT / 4 + 255) / 256, 256>>>(
        (const float4*)patches, (const float4*)db, (float4*)d_out);
}